// round 2
// baseline (speedup 1.0000x reference)
#include <cuda_runtime.h>
#include <mma.h>
#include <cstdint>

using namespace nvcuda;

#define N_NODES 50000
#define N_EDGES 600000
#define FEAT 128
#define PADM 50048   // 782 * 64, >= N_NODES

// ---------------- scratch (static device globals; no allocation) ----------------
__device__ int   g_idx64;                 // 1 if index inputs are int64, 0 if int32
__device__ int   g_cnt[N_NODES];
__device__ int   g_cursor[N_NODES];
__device__ int   g_rowstart[N_NODES + 1];
__device__ float g_inv[N_NODES];
__device__ int   g_csr[N_EDGES];
__device__ float g_xpad[(size_t)PADM * FEAT];
__device__ float g_h1  [(size_t)PADM * FEAT];
__device__ float g_agg [(size_t)PADM * FEAT];

__device__ __forceinline__ int load_idx(const void* p, long long i, int is64) {
    if (is64) return (int)((const long long*)p)[i];
    return ((const int*)p)[i];
}

// ---------------- dtype detection ----------------
// If edge_index is int64, every high 32-bit word is 0 (values in [0, 50000)).
// If int32, odd words are random edge endpoints -> virtually never all zero.
__global__ void k_detect(const unsigned* __restrict__ w) {
    if (threadIdx.x == 0 && blockIdx.x == 0) {
        int is64 = 1;
        for (int i = 0; i < 256; i++)
            if (w[2 * i + 1] != 0u) { is64 = 0; break; }
        g_idx64 = is64;
    }
}

// ---------------- small utility kernels ----------------
__global__ void k_zero_out(float* __restrict__ out, int n) {
    int stride = gridDim.x * blockDim.x;
    int i = blockIdx.x * blockDim.x + threadIdx.x;
    float4 z = make_float4(0.f, 0.f, 0.f, 0.f);
    float4* o4 = (float4*)out;
    int n4 = n >> 2;
    for (; i < n4; i += stride) o4[i] = z;
}

__global__ void k_setup(const float* __restrict__ x) {
    int stride = gridDim.x * blockDim.x;
    int total = PADM * FEAT;
    for (int i = blockIdx.x * blockDim.x + threadIdx.x; i < total; i += stride) {
        float v = (i < N_NODES * FEAT) ? x[i] : 0.f;
        g_xpad[i] = v;
        if (i >= N_NODES * FEAT) { g_h1[i] = 0.f; g_agg[i] = 0.f; }
        if (i < N_NODES) { g_cnt[i] = 0; g_cursor[i] = 0; }
    }
}

__global__ void k_hist(const void* __restrict__ ei) {
    int e = blockIdx.x * blockDim.x + threadIdx.x;
    if (e >= N_EDGES) return;
    int d = load_idx(ei, (long long)N_EDGES + e, g_idx64);
    if ((unsigned)d < (unsigned)N_NODES)
        atomicAdd(&g_cnt[d], 1);
}

// single-block exclusive scan of g_cnt -> g_rowstart, plus 1/max(cnt,1) -> g_inv
__global__ void k_scan() {
    __shared__ int warp_sums[32];
    __shared__ int s_carry;
    int tid = threadIdx.x;
    int lane = tid & 31;
    int wid = tid >> 5;
    if (tid == 0) s_carry = 0;
    __syncthreads();
    for (int base = 0; base < N_NODES; base += 1024) {
        int i = base + tid;
        int v = (i < N_NODES) ? g_cnt[i] : 0;
        int x = v;
        #pragma unroll
        for (int o = 1; o < 32; o <<= 1) {
            int t = __shfl_up_sync(0xFFFFFFFFu, x, o);
            if (lane >= o) x += t;
        }
        if (lane == 31) warp_sums[wid] = x;
        __syncthreads();
        if (wid == 0) {
            int s = warp_sums[lane];
            #pragma unroll
            for (int o = 1; o < 32; o <<= 1) {
                int t = __shfl_up_sync(0xFFFFFFFFu, s, o);
                if (lane >= o) s += t;
            }
            warp_sums[lane] = s;
        }
        __syncthreads();
        int warp_off = (wid == 0) ? 0 : warp_sums[wid - 1];
        if (i < N_NODES) {
            g_rowstart[i] = s_carry + warp_off + (x - v);
            g_inv[i] = 1.0f / fmaxf((float)v, 1.0f);
        }
        __syncthreads();
        if (tid == 0) s_carry += warp_sums[31];
        __syncthreads();
    }
    if (tid == 0) g_rowstart[N_NODES] = s_carry;
}

__global__ void k_scatter(const void* __restrict__ ei) {
    int e = blockIdx.x * blockDim.x + threadIdx.x;
    if (e >= N_EDGES) return;
    int is64 = g_idx64;
    int s = load_idx(ei, e, is64);
    int d = load_idx(ei, (long long)N_EDGES + e, is64);
    if ((unsigned)d >= (unsigned)N_NODES || (unsigned)s >= (unsigned)N_NODES) return;
    int p = g_rowstart[d] + atomicAdd(&g_cursor[d], 1);
    if (p < N_EDGES) g_csr[p] = s;
}

// one warp per destination node: mean of source rows
__global__ void k_agg(int layer2) {
    const float* __restrict__ feat = layer2 ? g_h1 : g_xpad;
    int gw = (blockIdx.x * blockDim.x + threadIdx.x) >> 5;
    int lane = threadIdx.x & 31;
    if (gw >= N_NODES) return;
    int s = g_rowstart[gw];
    int e = g_rowstart[gw + 1];
    float4 acc = make_float4(0.f, 0.f, 0.f, 0.f);
    for (int i = s; i < e; i++) {
        int src = g_csr[i];
        float4 v = *(const float4*)(feat + (size_t)src * FEAT + lane * 4);
        acc.x += v.x; acc.y += v.y; acc.z += v.z; acc.w += v.w;
    }
    float inv = g_inv[gw];
    acc.x *= inv; acc.y *= inv; acc.z *= inv; acc.w *= inv;
    *(float4*)(g_agg + (size_t)gw * FEAT + lane * 4) = acc;
}

// ---------------- 3xTF32 GEMM: out = relu(agg @ Bl + H @ Br + bias) ----------------
typedef wmma::fragment<wmma::matrix_a, 16, 16, 8, wmma::precision::tf32, wmma::row_major> FragA;
typedef wmma::fragment<wmma::matrix_b, 16, 16, 8, wmma::precision::tf32, wmma::row_major> FragB;
typedef wmma::fragment<wmma::accumulator, 16, 16, 8, float> FragC;

template <class F>
__device__ __forceinline__ void split_tf32(F& hi, F& lo) {
    #pragma unroll
    for (int e = 0; e < hi.num_elements; e++) {
        float v = hi.x[e];
        float vh = wmma::__float_to_tf32(v);
        hi.x[e] = vh;
        lo.x[e] = wmma::__float_to_tf32(v - vh);
    }
}

// Block: 64 (M) x 128 (N). 8 warps: 2 M-warps x 4 N-warps; warp tile 32x32.
__global__ void k_gemm(int layer2,
                       const float* __restrict__ Bl,   // [128,128] applied to agg
                       const float* __restrict__ Br,   // [128,128] applied to h
                       const float* __restrict__ bias, // [128]
                       float* __restrict__ final_out,  // used if layer2
                       const void* __restrict__ pos) {
    __shared__ float cs[64 * FEAT];

    const float* A1 = g_agg;
    const float* A2 = layer2 ? g_h1 : g_xpad;
    float* outp = layer2 ? final_out : g_h1;

    int m0 = blockIdx.x * 64;
    int warp = threadIdx.x >> 5;
    int wm = warp & 1;    // 0..1
    int wn = warp >> 1;   // 0..3

    FragC c[2][2];
    #pragma unroll
    for (int i = 0; i < 2; i++)
        #pragma unroll
        for (int j = 0; j < 2; j++)
            wmma::fill_fragment(c[i][j], 0.0f);

    #pragma unroll
    for (int half = 0; half < 2; half++) {
        const float* A = half ? A2 : A1;
        const float* B = half ? Br : Bl;
        const float* Abase = A + (size_t)(m0 + wm * 32) * FEAT;
        const float* Bbase = B + wn * 32;
        #pragma unroll 4
        for (int k = 0; k < FEAT; k += 8) {
            FragA ah[2], al[2];
            #pragma unroll
            for (int i = 0; i < 2; i++) {
                wmma::load_matrix_sync(ah[i], Abase + (size_t)i * 16 * FEAT + k, FEAT);
                al[i] = ah[i];
                split_tf32(ah[i], al[i]);
            }
            FragB bh[2], bl[2];
            #pragma unroll
            for (int j = 0; j < 2; j++) {
                wmma::load_matrix_sync(bh[j], Bbase + (size_t)k * FEAT + j * 16, FEAT);
                bl[j] = bh[j];
                split_tf32(bh[j], bl[j]);
            }
            #pragma unroll
            for (int i = 0; i < 2; i++)
                #pragma unroll
                for (int j = 0; j < 2; j++) {
                    wmma::mma_sync(c[i][j], ah[i], bh[j], c[i][j]);
                    wmma::mma_sync(c[i][j], al[i], bh[j], c[i][j]);
                    wmma::mma_sync(c[i][j], ah[i], bl[j], c[i][j]);
                }
        }
    }

    // stage to smem, then bias + relu + (optional) pos_idx scatter
    #pragma unroll
    for (int i = 0; i < 2; i++)
        #pragma unroll
        for (int j = 0; j < 2; j++)
            wmma::store_matrix_sync(&cs[(wm * 32 + i * 16) * FEAT + wn * 32 + j * 16],
                                    c[i][j], FEAT, wmma::mem_row_major);
    __syncthreads();

    int is64 = g_idx64;
    for (int idx = threadIdx.x; idx < 64 * FEAT; idx += blockDim.x) {
        int m = idx >> 7;
        int n = idx & 127;
        int row = m0 + m;
        if (row < N_NODES) {
            float v = cs[idx] + bias[n];
            v = fmaxf(v, 0.0f);
            long long orow = layer2 ? (long long)load_idx(pos, row, is64) : (long long)row;
            outp[(size_t)orow * FEAT + n] = v;
        }
    }
}

// ---------------- launch ----------------
extern "C" void kernel_launch(void* const* d_in, const int* in_sizes, int n_in,
                              void* d_out, int out_size) {
    // inputs: x, edge_index, pos_idx, pad_n(scalar), Wl1, Wr1, b1, Wl2, Wr2, b2
    int wi = 3;
    if (n_in >= 10) wi = 4;  // pad_n present as an input
    const float* x   = (const float*)d_in[0];
    const void*  ei  = d_in[1];
    const void*  pos = d_in[2];
    const float* Wl1 = (const float*)d_in[wi + 0];
    const float* Wr1 = (const float*)d_in[wi + 1];
    const float* b1  = (const float*)d_in[wi + 2];
    const float* Wl2 = (const float*)d_in[wi + 3];
    const float* Wr2 = (const float*)d_in[wi + 4];
    const float* b2  = (const float*)d_in[wi + 5];
    float* out = (float*)d_out;

    k_detect<<<1, 32>>>((const unsigned*)ei);
    k_zero_out<<<2048, 256>>>(out, out_size);
    k_setup<<<4096, 256>>>(x);
    k_hist<<<(N_EDGES + 255) / 256, 256>>>(ei);
    k_scan<<<1, 1024>>>();
    k_scatter<<<(N_EDGES + 255) / 256, 256>>>(ei);

    // layer 1
    k_agg<<<(N_NODES + 7) / 8, 256>>>(0);
    k_gemm<<<PADM / 64, 256>>>(0, Wl1, Wr1, b1, nullptr, nullptr);
    // layer 2
    k_agg<<<(N_NODES + 7) / 8, 256>>>(1);
    k_gemm<<<PADM / 64, 256>>>(1, Wl2, Wr2, b2, out, pos);
}